// round 3
// baseline (speedup 1.0000x reference)
#include <cuda_runtime.h>
#include <math.h>

// ---------------------------------------------------------------------------
// Problem constants: B=8, C=64, H=W=32, HW=1024, D=32
// ---------------------------------------------------------------------------
static constexpr long M8 = 8ll * 1024 * 1024;

// Scratch: 7 big [8,1024,1024] buffers (56M) + small pool (~5.9M) = 64.6M floats.
// Size to 68M floats (272 MB) for margin.
__device__ float g_buf[68ll * 1024 * 1024];

// ---------------------------------------------------------------------------
// Generic batched SGEMM: C[b] (MxN) = opA(A[b]) * opB(B[b]) (+ bias[m])
//   TA=false: A is MxK row-major   TA=true: A is KxM row-major (A^T logical)
//   TB=false: B is KxN row-major   TB=true:  B is NxK row-major (C = A * B^T)
// Tile 128x128, KT=16, 256 threads, 8x8 microtile.
// Requires K % 16 == 0, M,N % 8 == 0 (all call sites satisfy this).
// ---------------------------------------------------------------------------
template <bool TA, bool TB>
__global__ void __launch_bounds__(256, 2)
gemm_kernel(const float* __restrict__ A, const float* __restrict__ B,
            float* __restrict__ Cmat, const float* __restrict__ bias,
            int M, int N, int K, long sA, long sB, long sC)
{
    __shared__ float As[16][128];
    __shared__ float Bs[16][128];

    const int tid = threadIdx.x;
    const int m0 = blockIdx.y * 128;
    const int n0 = blockIdx.x * 128;
    const float* Ab = A + (long)blockIdx.z * sA;
    const float* Bb = B + (long)blockIdx.z * sB;
    float* Cb = Cmat + (long)blockIdx.z * sC;

    float acc[8][8];
#pragma unroll
    for (int i = 0; i < 8; i++)
#pragma unroll
        for (int j = 0; j < 8; j++) acc[i][j] = 0.f;

    const int rowt = (tid >> 4) * 8;
    const int colt = (tid & 15) * 8;

    for (int k0 = 0; k0 < K; k0 += 16) {
        // ---- load A tile into As[k][m] ----
        if (!TA) {
            int ar = tid >> 1;
            int ac = (tid & 1) * 8;
            float4 v0 = {0.f,0.f,0.f,0.f}, v1 = {0.f,0.f,0.f,0.f};
            if (m0 + ar < M) {
                const float* p = Ab + (long)(m0 + ar) * K + k0 + ac;
                v0 = *(const float4*)p;
                v1 = *(const float4*)(p + 4);
            }
            As[ac+0][ar] = v0.x; As[ac+1][ar] = v0.y; As[ac+2][ar] = v0.z; As[ac+3][ar] = v0.w;
            As[ac+4][ar] = v1.x; As[ac+5][ar] = v1.y; As[ac+6][ar] = v1.z; As[ac+7][ar] = v1.w;
        } else {
            int kr = tid >> 4;
            int mc = (tid & 15) * 8;
            float4 v0 = {0.f,0.f,0.f,0.f}, v1 = {0.f,0.f,0.f,0.f};
            if (m0 + mc < M) {
                const float* p = Ab + (long)(k0 + kr) * M + m0 + mc;
                v0 = *(const float4*)p;
                v1 = *(const float4*)(p + 4);
            }
            *(float4*)&As[kr][mc]     = v0;
            *(float4*)&As[kr][mc + 4] = v1;
        }
        // ---- load B tile into Bs[k][n] ----
        if (TB) {
            int br = tid >> 1;
            int bc = (tid & 1) * 8;
            float4 v0 = {0.f,0.f,0.f,0.f}, v1 = {0.f,0.f,0.f,0.f};
            if (n0 + br < N) {
                const float* p = Bb + (long)(n0 + br) * K + k0 + bc;
                v0 = *(const float4*)p;
                v1 = *(const float4*)(p + 4);
            }
            Bs[bc+0][br] = v0.x; Bs[bc+1][br] = v0.y; Bs[bc+2][br] = v0.z; Bs[bc+3][br] = v0.w;
            Bs[bc+4][br] = v1.x; Bs[bc+5][br] = v1.y; Bs[bc+6][br] = v1.z; Bs[bc+7][br] = v1.w;
        } else {
            int kr = tid >> 4;
            int nc = (tid & 15) * 8;
            float4 v0 = {0.f,0.f,0.f,0.f}, v1 = {0.f,0.f,0.f,0.f};
            if (n0 + nc < N) {
                const float* p = Bb + (long)(k0 + kr) * N + n0 + nc;
                v0 = *(const float4*)p;
                v1 = *(const float4*)(p + 4);
            }
            *(float4*)&Bs[kr][nc]     = v0;
            *(float4*)&Bs[kr][nc + 4] = v1;
        }
        __syncthreads();

#pragma unroll
        for (int kk = 0; kk < 16; kk++) {
            float4 a0 = *(const float4*)&As[kk][rowt];
            float4 a1 = *(const float4*)&As[kk][rowt + 4];
            float4 b0 = *(const float4*)&Bs[kk][colt];
            float4 b1 = *(const float4*)&Bs[kk][colt + 4];
            float ra[8] = {a0.x,a0.y,a0.z,a0.w,a1.x,a1.y,a1.z,a1.w};
            float rb[8] = {b0.x,b0.y,b0.z,b0.w,b1.x,b1.y,b1.z,b1.w};
#pragma unroll
            for (int i = 0; i < 8; i++)
#pragma unroll
                for (int j = 0; j < 8; j++)
                    acc[i][j] += ra[i] * rb[j];
        }
        __syncthreads();
    }

#pragma unroll
    for (int i = 0; i < 8; i++) {
        int m = m0 + rowt + i;
        if (m < M) {
            float bv = bias ? bias[m] : 0.f;
            int n = n0 + colt;
            if (n < N) {
                float4 o0 = make_float4(acc[i][0]+bv, acc[i][1]+bv, acc[i][2]+bv, acc[i][3]+bv);
                float4 o1 = make_float4(acc[i][4]+bv, acc[i][5]+bv, acc[i][6]+bv, acc[i][7]+bv);
                float* cp = Cb + (long)m * N + n;
                *(float4*)cp       = o0;
                *(float4*)(cp + 4) = o1;
            }
        }
    }
}

// ---------------------------------------------------------------------------
// Row softmax: one block per row. A = softmax(L) rowwise.
// ---------------------------------------------------------------------------
__global__ void row_softmax_k(const float* __restrict__ L, float* __restrict__ A, int N)
{
    long row = blockIdx.x;
    const float* p = L + row * (long)N;
    float* q = A + row * (long)N;
    int t = threadIdx.x;
    __shared__ float sh[8];

    float m = -3.4e38f;
    for (int i = t; i < N; i += 256) m = fmaxf(m, p[i]);
#pragma unroll
    for (int o = 16; o; o >>= 1) m = fmaxf(m, __shfl_xor_sync(0xffffffffu, m, o));
    if ((t & 31) == 0) sh[t >> 5] = m;
    __syncthreads();
    float mm = sh[0];
#pragma unroll
    for (int w = 1; w < 8; w++) mm = fmaxf(mm, sh[w]);
    __syncthreads();

    float s = 0.f;
    for (int i = t; i < N; i += 256) s += expf(p[i] - mm);
#pragma unroll
    for (int o = 16; o; o >>= 1) s += __shfl_xor_sync(0xffffffffu, s, o);
    if ((t & 31) == 0) sh[t >> 5] = s;
    __syncthreads();
    float ss = 0.f;
#pragma unroll
    for (int w = 0; w < 8; w++) ss += sh[w];
    float inv = 1.f / ss;

    for (int i = t; i < N; i += 256) q[i] = expf(p[i] - mm) * inv;
}

// ---------------------------------------------------------------------------
// Column softmax of L [8][1024][1024], written in the SAME (k,i) layout:
//   AT[b,k,i] = exp(L[b,k,i] - max_k) / sum_k   (== attn(x2f,x1f) transposed)
// Block: 256 threads = 64 columns x 4 k-groups. Grid (16, 8).
// ---------------------------------------------------------------------------
__global__ void col_softmax_T_k(const float* __restrict__ L, float* __restrict__ AT)
{
    int c  = threadIdx.x & 63;
    int kg = threadIdx.x >> 6;
    int i  = blockIdx.x * 64 + c;
    const float* Lb = L  + (long)blockIdx.y * 1048576;
    float*       Ab = AT + (long)blockIdx.y * 1048576;
    __shared__ float red[4][64];

    float m = -3.4e38f;
    for (int k = kg; k < 1024; k += 4) m = fmaxf(m, Lb[(k << 10) + i]);
    red[kg][c] = m;
    __syncthreads();
    m = fmaxf(fmaxf(red[0][c], red[1][c]), fmaxf(red[2][c], red[3][c]));
    __syncthreads();

    float s = 0.f;
    for (int k = kg; k < 1024; k += 4) s += expf(Lb[(k << 10) + i] - m);
    red[kg][c] = s;
    __syncthreads();
    s = red[0][c] + red[1][c] + red[2][c] + red[3][c];
    float inv = 1.f / s;

    for (int k = kg; k < 1024; k += 4)
        Ab[(k << 10) + i] = expf(Lb[(k << 10) + i] - m) * inv;
}

// ---------------------------------------------------------------------------
// Keys cubic kernel, a = -0.5 (matches jax _fill_keys_cubic_kernel)
// ---------------------------------------------------------------------------
__device__ __forceinline__ float keys_cubic(float x)
{
    x = fabsf(x);
    if (x < 1.f) return ((1.5f * x - 2.5f) * x) * x + 1.f;
    if (x < 2.f) return ((-0.5f * x + 2.5f) * x - 4.f) * x + 2.f;
    return 0.f;
}

// Bicubic downsample by 2 with antialias (kernel_scale=2, 8 taps/dim),
// weights renormalized over in-range taps (== jax weight-matrix normalization).
// x: [8,64,32,32] -> y: [8,64,16,16]
__global__ void downsample_k(const float* __restrict__ x, float* __restrict__ y)
{
    int idx = blockIdx.x * 256 + threadIdx.x;
    if (idx >= 8 * 64 * 256) return;
    int ox = idx & 15;
    int oy = (idx >> 4) & 15;
    int bc = idx >> 8;

    int jy0 = 2 * oy - 3, jx0 = 2 * ox - 3;
    float wy[8], wx[8];
    float sy = 0.f, sx = 0.f;
#pragma unroll
    for (int t = 0; t < 8; t++) {
        float w = keys_cubic(fabsf(3.5f - t) * 0.5f);
        int jy = jy0 + t;
        wy[t] = (jy >= 0 && jy < 32) ? w : 0.f; sy += wy[t];
        int jx = jx0 + t;
        wx[t] = (jx >= 0 && jx < 32) ? w : 0.f; sx += wx[t];
    }
    float iy = 1.f / sy, ix = 1.f / sx;
#pragma unroll
    for (int t = 0; t < 8; t++) { wy[t] *= iy; wx[t] *= ix; }

    const float* src = x + (long)bc * 1024;
    float acc = 0.f;
#pragma unroll
    for (int t = 0; t < 8; t++) {
        int jy = min(max(jy0 + t, 0), 31);
        float r = 0.f;
#pragma unroll
        for (int u = 0; u < 8; u++) {
            int jx = min(max(jx0 + u, 0), 31);
            r += wx[u] * src[jy * 32 + jx];
        }
        acc += wy[t] * r;
    }
    y[idx] = acc;
}

// Bicubic upsample x4 (4 taps/dim), src [8,256,256] -> dst [8,1024,1024]
__global__ void upsample_k(const float* __restrict__ s, float* __restrict__ d)
{
    long idx = (long)blockIdx.x * 256 + threadIdx.x;
    if (idx >= 8ll * 1024 * 1024) return;
    int J = (int)(idx & 1023);
    int I = (int)((idx >> 10) & 1023);
    int b = (int)(idx >> 20);

    int i0, j0;
    float wi[4], wj[4];
    {
        float sf = (I + 0.5f) * 0.25f - 0.5f;
        float fl = floorf(sf);
        float f  = sf - fl;
        int base = (int)fl - 1;
        float tot = 0.f;
#pragma unroll
        for (int t = 0; t < 4; t++) {
            float w = keys_cubic(f + 1.f - t);
            int j = base + t;
            if (j < 0 || j >= 256) w = 0.f;
            wi[t] = w; tot += w;
        }
        float inv = 1.f / tot;
#pragma unroll
        for (int t = 0; t < 4; t++) wi[t] *= inv;
        i0 = base;
    }
    {
        float sf = (J + 0.5f) * 0.25f - 0.5f;
        float fl = floorf(sf);
        float f  = sf - fl;
        int base = (int)fl - 1;
        float tot = 0.f;
#pragma unroll
        for (int t = 0; t < 4; t++) {
            float w = keys_cubic(f + 1.f - t);
            int j = base + t;
            if (j < 0 || j >= 256) w = 0.f;
            wj[t] = w; tot += w;
        }
        float inv = 1.f / tot;
#pragma unroll
        for (int t = 0; t < 4; t++) wj[t] *= inv;
        j0 = base;
    }

    const float* sp = s + (long)b * 65536;
    float acc = 0.f;
#pragma unroll
    for (int t = 0; t < 4; t++) {
        int ii = min(max(i0 + t, 0), 255);
        float r = 0.f;
#pragma unroll
        for (int u = 0; u < 4; u++) {
            int jj = min(max(j0 + u, 0), 255);
            r += wj[u] * sp[ii * 256 + jj];
        }
        acc += wi[t] * r;
    }
    d[idx] = acc;
}

// ---------------------------------------------------------------------------
// BatchNorm stats per channel over (B, HW): T [8,64,1024] -> mv[c]=mean, mv[64+c]=var
// ---------------------------------------------------------------------------
__global__ void bn_stats_k(const float* __restrict__ T, float* __restrict__ mv)
{
    int c = blockIdx.x;
    int t = threadIdx.x;
    float s = 0.f, s2 = 0.f;
    for (int i = t; i < 8192; i += 256) {
        float v = T[(long)(i >> 10) * 65536 + c * 1024 + (i & 1023)];
        s += v; s2 += v * v;
    }
    __shared__ float sh1[8], sh2[8];
#pragma unroll
    for (int o = 16; o; o >>= 1) {
        s  += __shfl_xor_sync(0xffffffffu, s, o);
        s2 += __shfl_xor_sync(0xffffffffu, s2, o);
    }
    if ((t & 31) == 0) { sh1[t >> 5] = s; sh2[t >> 5] = s2; }
    __syncthreads();
    if (t == 0) {
        float ts = 0.f, ts2 = 0.f;
#pragma unroll
        for (int w = 0; w < 8; w++) { ts += sh1[w]; ts2 += sh2[w]; }
        float mean = ts * (1.f / 8192.f);
        float var  = ts2 * (1.f / 8192.f) - mean * mean;
        mv[c] = mean;
        mv[64 + c] = fmaxf(var, 0.f);
    }
}

// ---------------------------------------------------------------------------
// Finalize: res = 0.5*(relu(BN(ch_o)+x) + relu(BN(hw_o)+x)); out = [res1 ; res2]
// ---------------------------------------------------------------------------
__global__ void finalize_k(const float* __restrict__ x1, const float* __restrict__ x2,
                           const float* __restrict__ ch1o, const float* __restrict__ ch2o,
                           const float* __restrict__ hw1o, const float* __restrict__ hw2o,
                           const float* __restrict__ mv,
                           const float* __restrict__ gamma, const float* __restrict__ beta,
                           float* __restrict__ out)
{
    int idx = blockIdx.x * 256 + threadIdx.x;
    if (idx >= 524288) return;
    int c = (idx >> 10) & 63;
    float g = gamma[c], be = beta[c];

    float xa = x1[idx], xb = x2[idx];

    float v, r;
    v = (ch1o[idx] - mv[c])       * rsqrtf(mv[64 + c]  + 1e-5f) * g + be + xa;
    r = fmaxf(v, 0.f);
    v = (hw1o[idx] - mv[256 + c]) * rsqrtf(mv[320 + c] + 1e-5f) * g + be + xa;
    out[idx] = 0.5f * (r + fmaxf(v, 0.f));

    v = (ch2o[idx] - mv[128 + c]) * rsqrtf(mv[192 + c] + 1e-5f) * g + be + xb;
    r = fmaxf(v, 0.f);
    v = (hw2o[idx] - mv[384 + c]) * rsqrtf(mv[448 + c] + 1e-5f) * g + be + xb;
    out[524288 + idx] = 0.5f * (r + fmaxf(v, 0.f));
}

// ---------------------------------------------------------------------------
// Host-side GEMM dispatch
// ---------------------------------------------------------------------------
static void launch_gemm(bool ta, bool tb,
                        const float* A, const float* B, float* C, const float* bias,
                        int M, int N, int K, long sA, long sB, long sC, int batch)
{
    dim3 grid((N + 127) / 128, (M + 127) / 128, batch);
    if (!ta && !tb)      gemm_kernel<false, false><<<grid, 256>>>(A, B, C, bias, M, N, K, sA, sB, sC);
    else if (!ta && tb)  gemm_kernel<false, true ><<<grid, 256>>>(A, B, C, bias, M, N, K, sA, sB, sC);
    else if (ta && !tb)  gemm_kernel<true,  false><<<grid, 256>>>(A, B, C, bias, M, N, K, sA, sB, sC);
    else                 gemm_kernel<true,  true ><<<grid, 256>>>(A, B, C, bias, M, N, K, sA, sB, sC);
}

extern "C" void kernel_launch(void* const* d_in, const int* in_sizes, int n_in,
                              void* d_out, int out_size)
{
    const float* x1     = (const float*)d_in[0];   // [8,64,32,32]
    const float* x2     = (const float*)d_in[1];
    const float* w_down = (const float*)d_in[2];   // [32,64]
    const float* b_down = (const float*)d_in[3];   // [32]
    const float* w_up   = (const float*)d_in[4];   // [64,32]
    const float* b_up   = (const float*)d_in[5];   // [64]
    const float* gamma  = (const float*)d_in[6];   // [64]
    const float* beta   = (const float*)d_in[7];   // [64]
    float* out = (float*)d_out;

    float* base = nullptr;
    cudaGetSymbolAddress((void**)&base, g_buf);

    // Big [8M] buffers, with reuse: HW1 aliases X1F, HW2 aliases X2F
    // (X1F/X2F are dead once LB is computed; LB is dead once softmaxes run).
    float* X1F  = base + 0 * M8;
    float* X2F  = base + 1 * M8;
    float* LB   = base + 2 * M8;
    float* A12  = base + 3 * M8;
    float* A21T = base + 4 * M8;
    float* UP1  = base + 5 * M8;
    float* UP2  = base + 6 * M8;
    float* HW1  = X1F;   // reuse
    float* HW2  = X2F;   // reuse

    float* S = base + 7 * M8;   // small pool: ~5.86M floats, fits in 68M total
    float* XD1   = S; S += 262144;
    float* XD2   = S; S += 262144;
    float* X1C   = S; S += 32768;
    float* X2C   = S; S += 32768;
    float* X1CD  = S; S += 8192;
    float* X2CD  = S; S += 8192;
    float* LC    = S; S += 32768;
    float* AC12  = S; S += 32768;
    float* AC21  = S; S += 32768;
    float* LCD   = S; S += 8192;
    float* ACD12 = S; S += 8192;
    float* ACD21 = S; S += 8192;
    float* TT    = S; S += 16384;
    float* U1T   = S; S += 32768;
    float* U2T   = S; S += 32768;
    float* CH1   = S; S += 32768;
    float* CH2   = S; S += 32768;
    float* CH1O  = S; S += 524288;
    float* CH2O  = S; S += 524288;
    float* XDN1  = S; S += 131072;
    float* XDN2  = S; S += 131072;
    float* X1FD  = S; S += 524288;
    float* X2FD  = S; S += 524288;
    float* LFD   = S; S += 524288;
    float* AFD12 = S; S += 524288;
    float* AFD21 = S; S += 524288;
    float* HW1O  = S; S += 524288;
    float* HW2O  = S; S += 524288;
    float* MV    = S; S += 512;

    // ===================== channel path =====================
    // channel grams: G = X X^T, X=[64,1024]
    launch_gemm(false, true, x1, x1, X1C, nullptr, 64, 64, 1024, 65536, 65536, 4096, 8);
    launch_gemm(false, true, x2, x2, X2C, nullptr, 64, 64, 1024, 65536, 65536, 4096, 8);
    // down_ch: XD = w_down @ X + b_down   [8,32,1024]
    launch_gemm(false, false, w_down, x1, XD1, b_down, 32, 1024, 64, 0, 65536, 32768, 8);
    launch_gemm(false, false, w_down, x2, XD2, b_down, 32, 1024, 64, 0, 65536, 32768, 8);
    // down channel grams [8,32,32]
    launch_gemm(false, true, XD1, XD1, X1CD, nullptr, 32, 32, 1024, 32768, 32768, 1024, 8);
    launch_gemm(false, true, XD2, XD2, X2CD, nullptr, 32, 32, 1024, 32768, 32768, 1024, 8);
    // channel attentions
    launch_gemm(false, true, X1C, X2C, LC, nullptr, 64, 64, 64, 4096, 4096, 4096, 8);
    row_softmax_k<<<512, 256>>>(LC, AC12, 64);
    launch_gemm(false, true, X2C, X1C, LC, nullptr, 64, 64, 64, 4096, 4096, 4096, 8);
    row_softmax_k<<<512, 256>>>(LC, AC21, 64);
    // down channel attentions
    launch_gemm(false, true, X1CD, X2CD, LCD, nullptr, 32, 32, 32, 1024, 1024, 1024, 8);
    row_softmax_k<<<256, 256>>>(LCD, ACD12, 32);
    launch_gemm(false, true, X2CD, X1CD, LCD, nullptr, 32, 32, 32, 1024, 1024, 1024, 8);
    row_softmax_k<<<256, 256>>>(LCD, ACD21, 32);
    // up_channel: T = w_up@A + b_up ; U^T = w_up @ T^T + b_up (per-row bias)
    launch_gemm(false, false, w_up, ACD12, TT, b_up, 64, 32, 32, 0, 1024, 2048, 8);
    launch_gemm(false, true,  w_up, TT, U1T, b_up, 64, 64, 32, 0, 2048, 4096, 8);
    launch_gemm(false, false, w_up, ACD21, TT, b_up, 64, 32, 32, 0, 1024, 2048, 8);
    launch_gemm(false, true,  w_up, TT, U2T, b_up, 64, 64, 32, 0, 2048, 4096, 8);
    // ch = Attn @ U  (U stored transposed -> NT)
    launch_gemm(false, true, AC12, U1T, CH1, nullptr, 64, 64, 64, 4096, 4096, 4096, 8);
    launch_gemm(false, true, AC21, U2T, CH2, nullptr, 64, 64, 64, 4096, 4096, 4096, 8);
    // ch_o = ch @ xflat  [8,64,1024]
    launch_gemm(false, false, CH1, x1, CH1O, nullptr, 64, 1024, 64, 4096, 65536, 65536, 8);
    launch_gemm(false, false, CH2, x2, CH2O, nullptr, 64, 1024, 64, 4096, 65536, 65536, 8);

    // ===================== feature path =====================
    // feature grams: G = X^T X  (TN, A=B=X[64,1024])
    launch_gemm(true, false, x1, x1, X1F, nullptr, 1024, 1024, 64, 65536, 65536, 1048576, 8);
    launch_gemm(true, false, x2, x2, X2F, nullptr, 1024, 1024, 64, 65536, 65536, 1048576, 8);
    // bicubic downsample 32->16
    downsample_k<<<512, 256>>>(x1, XDN1);
    downsample_k<<<512, 256>>>(x2, XDN2);
    // down feature grams [8,256,256]
    launch_gemm(true, false, XDN1, XDN1, X1FD, nullptr, 256, 256, 64, 16384, 16384, 65536, 8);
    launch_gemm(true, false, XDN2, XDN2, X2FD, nullptr, 256, 256, 64, 16384, 16384, 65536, 8);
    // down feature attentions
    launch_gemm(false, true, X1FD, X2FD, LFD, nullptr, 256, 256, 256, 65536, 65536, 65536, 8);
    row_softmax_k<<<2048, 256>>>(LFD, AFD12, 256);
    launch_gemm(false, true, X2FD, X1FD, LFD, nullptr, 256, 256, 256, 65536, 65536, 65536, 8);
    row_softmax_k<<<2048, 256>>>(LFD, AFD21, 256);
    // bicubic upsample x4 of attention maps
    upsample_k<<<32768, 256>>>(AFD12, UP1);
    upsample_k<<<32768, 256>>>(AFD21, UP2);
    // big logits L = x1f @ x2f^T   (shared by both directions)
    launch_gemm(false, true, X1F, X2F, LB, nullptr, 1024, 1024, 1024, 1048576, 1048576, 1048576, 8);
    row_softmax_k<<<8192, 256>>>(LB, A12, 1024);
    {
        dim3 g(16, 8);
        col_softmax_T_k<<<g, 256>>>(LB, A21T);
    }
    // hw1 = A12 @ up1 (NN), hw2 = A21 @ up2 (TN with transposed-stored A21)
    // NOTE: HW1 aliases X1F, HW2 aliases X2F — both dead after LB gemm above.
    launch_gemm(false, false, A12, UP1, HW1, nullptr, 1024, 1024, 1024, 1048576, 1048576, 1048576, 8);
    launch_gemm(true,  false, A21T, UP2, HW2, nullptr, 1024, 1024, 1024, 1048576, 1048576, 1048576, 8);
    // hw_o[c,p] = sum_q x[c,q] hw[p,q]  -> NT
    launch_gemm(false, true, x1, HW1, HW1O, nullptr, 64, 1024, 1024, 65536, 1048576, 65536, 8);
    launch_gemm(false, true, x2, HW2, HW2O, nullptr, 64, 1024, 1024, 65536, 1048576, 65536, 8);

    // ===================== BN + residual + relu + average =====================
    bn_stats_k<<<64, 256>>>(CH1O, MV);
    bn_stats_k<<<64, 256>>>(CH2O, MV + 128);
    bn_stats_k<<<64, 256>>>(HW1O, MV + 256);
    bn_stats_k<<<64, 256>>>(HW2O, MV + 384);
    finalize_k<<<2048, 256>>>(x1, x2, CH1O, CH2O, HW1O, HW2O, MV, gamma, beta, out);
}